// round 8
// baseline (speedup 1.0000x reference)
#include <cuda_runtime.h>
#include <math.h>
#include <cstdint>

#define LSEQ   2048
#define NB     4
#define DMODEL 1024
#define NH     16
#define HSIZE  64
#define MROWS  (NB*LSEQ)   // 8192

// Scratch (allocation-free rule: __device__ globals)
__device__ float g_Q[(size_t)NB*NH*LSEQ*HSIZE];
__device__ float g_K[(size_t)NB*NH*LSEQ*HSIZE];
__device__ float g_V[(size_t)NB*NH*LSEQ*HSIZE];
__device__ float g_Y[(size_t)MROWS*DMODEL];

// ---------------------------------------------------------------------------
// Kernel 1: qkv = x @ W_attn + b_attn, scattered into head-major Q/K/V.
// 128x128 tile, BK=8, 256 threads, 8x8 microtile as 2x2 quads of 4
// (conflict-free smem banking), double-buffered smem.
// Warp grid 2x4 (wm,wn); lane grid 8x4 (lr,lc).
//   m chunks: wm*64 + lr*4 (+32)      n chunks: wn*32 + lc*4 (+16)
// ---------------------------------------------------------------------------
__global__ __launch_bounds__(256, 2) void gemm_qkv_kernel(
    const float* __restrict__ X, const float* __restrict__ W,
    const float* __restrict__ bias)
{
    __shared__ float As[2][8][128];
    __shared__ float Bs[2][8][128];
    const int tid  = threadIdx.x;
    const int wid  = tid >> 5;
    const int lane = tid & 31;
    const int wm   = wid >> 2;          // 0..1
    const int wn   = wid & 3;           // 0..3
    const int lr   = lane >> 2;         // 0..7
    const int lc   = lane & 3;          // 0..3
    const int m0   = blockIdx.y * 128;
    const int n0   = blockIdx.x * 128;
    const int aBase = wm*64 + lr*4;     // + {0,32}
    const int bBase = wn*32 + lc*4;     // + {0,16}

    const int aRow = tid >> 1;          // 0..127
    const int aCol = (tid & 1) << 2;    // 0 or 4
    const int bRow = tid >> 5;          // 0..7
    const int bCol = (tid & 31) << 2;   // 0..124

    const float* Ap = X + (size_t)(m0 + aRow) * DMODEL + aCol;
    const float* Bp = W + (size_t)bRow * 3072 + n0 + bCol;

    float acc[8][8];
    #pragma unroll
    for (int i = 0; i < 8; i++)
        #pragma unroll
        for (int j = 0; j < 8; j++) acc[i][j] = 0.f;

    // prologue: tile 0 -> buffer 0
    {
        float4 av = *(const float4*)(Ap);
        float4 bv = *(const float4*)(Bp);
        As[0][aCol+0][aRow] = av.x;
        As[0][aCol+1][aRow] = av.y;
        As[0][aCol+2][aRow] = av.z;
        As[0][aCol+3][aRow] = av.w;
        *(float4*)&Bs[0][bRow][bCol] = bv;
    }
    __syncthreads();

    const int NT = DMODEL / 8;   // 128
    for (int t = 0; t < NT; t++) {
        const int buf = t & 1;
        float4 anext, bnext;
        if (t + 1 < NT) {
            anext = *(const float4*)(Ap + (t+1)*8);
            bnext = *(const float4*)(Bp + (size_t)(t+1)*8*3072);
        }
        #pragma unroll
        for (int kk = 0; kk < 8; kk++) {
            float a[8], b[8];
            *(float4*)&a[0] = *(const float4*)&As[buf][kk][aBase];
            *(float4*)&a[4] = *(const float4*)&As[buf][kk][aBase + 32];
            *(float4*)&b[0] = *(const float4*)&Bs[buf][kk][bBase];
            *(float4*)&b[4] = *(const float4*)&Bs[buf][kk][bBase + 16];
            #pragma unroll
            for (int i = 0; i < 8; i++)
                #pragma unroll
                for (int j = 0; j < 8; j++)
                    acc[i][j] = fmaf(a[i], b[j], acc[i][j]);
        }
        if (t + 1 < NT) {
            const int nb = buf ^ 1;
            As[nb][aCol+0][aRow] = anext.x;
            As[nb][aCol+1][aRow] = anext.y;
            As[nb][aCol+2][aRow] = anext.z;
            As[nb][aCol+3][aRow] = anext.w;
            *(float4*)&Bs[nb][bRow][bCol] = bnext;
        }
        __syncthreads();
    }

    // Epilogue: scatter into head-major Q/K/V.
    const int chunk = n0 >> 10;
    float* dst = (chunk == 0) ? g_Q : (chunk == 1) ? g_K : g_V;
    #pragma unroll
    for (int i = 0; i < 8; i++) {
        const int m  = m0 + aBase + ((i < 4) ? i : (28 + i));  // +32 chunk
        const int bb = m >> 11;
        const int l  = m & (LSEQ - 1);
        #pragma unroll
        for (int j4 = 0; j4 < 8; j4 += 4) {
            const int n = n0 + bBase + ((j4 == 0) ? 0 : 16);
            const int d = n - (chunk << 10);
            const int h = d >> 6;
            const int e = d & 63;
            float4 ov;
            ov.x = acc[i][j4+0] + bias[n+0];
            ov.y = acc[i][j4+1] + bias[n+1];
            ov.z = acc[i][j4+2] + bias[n+2];
            ov.w = acc[i][j4+3] + bias[n+3];
            *(float4*)&dst[((((size_t)bb*NH + h)*LSEQ + l) << 6) + e] = ov;
        }
    }
}

// ---------------------------------------------------------------------------
// Kernel 2: fused causal flash attention with relative-position band
// (byte-identical to the R2 passing version).
// Srel[i,j] = q_i . Er[L-1-i+j]  (j <= i), fused as  q . (k + er).
// ---------------------------------------------------------------------------
__global__ __launch_bounds__(256) void attn_kernel(const float* __restrict__ Er)
{
    extern __shared__ float sm[];
    float* qT  = sm;            // [64][68]  qT[d][i]
    float* kT  = sm + 4352;     // [64][68]  kT[d][j]
    float* vS  = sm + 8704;     // [64][68]  vS[j][e]
    float* pT  = sm + 13056;    // [64][68]  pT[j][i]
    float* erS = sm + 17408;    // [64][132] erS[d][m], m in [0,127]

    const int tid = threadIdx.x;
    const int tx  = tid & 15;
    const int ty  = tid >> 4;
    const int qt  = blockIdx.x;
    const int bh  = blockIdx.y;
    const int i0  = qt << 6;

    const float* Qb = g_Q + (size_t)bh * LSEQ * HSIZE;
    const float* Kb = g_K + (size_t)bh * LSEQ * HSIZE;
    const float* Vb = g_V + (size_t)bh * LSEQ * HSIZE;

    #pragma unroll
    for (int r = 0; r < 4; r++) {
        int idx = tid + (r << 8);
        int row = idx >> 4;
        int f   = (idx & 15) << 2;
        float4 v = *(const float4*)(Qb + (size_t)(i0 + row) * HSIZE + f);
        qT[(f+0)*68 + row] = v.x;
        qT[(f+1)*68 + row] = v.y;
        qT[(f+2)*68 + row] = v.z;
        qT[(f+3)*68 + row] = v.w;
    }

    float mrow[4], lrow[4], o[4][4];
    #pragma unroll
    for (int a = 0; a < 4; a++) {
        mrow[a] = -INFINITY;
        lrow[a] = 0.f;
        #pragma unroll
        for (int e = 0; e < 4; e++) o[a][e] = 0.f;
    }
    const int erBase = 60 + ((tx - ty) << 2);

    for (int kt = 0; kt <= qt; kt++) {
        const int j0 = kt << 6;
        __syncthreads();
        #pragma unroll
        for (int r = 0; r < 4; r++) {
            int idx = tid + (r << 8);
            int row = idx >> 4;
            int f   = (idx & 15) << 2;
            float4 kv = *(const float4*)(Kb + (size_t)(j0 + row) * HSIZE + f);
            kT[(f+0)*68 + row] = kv.x;
            kT[(f+1)*68 + row] = kv.y;
            kT[(f+2)*68 + row] = kv.z;
            kT[(f+3)*68 + row] = kv.w;
            float4 vv = *(const float4*)(Vb + (size_t)(j0 + row) * HSIZE + f);
            *(float4*)&vS[row*68 + f] = vv;
        }
        const int m_lo = LSEQ - 64 - i0 + j0;
        #pragma unroll
        for (int r = 0; r < 8; r++) {
            int idx = tid + (r << 8);
            int mm  = idx >> 4;
            int f   = (idx & 15) << 2;
            int mg  = m_lo + mm;
            float4 ev = make_float4(0.f, 0.f, 0.f, 0.f);
            if (mg < LSEQ)
                ev = *(const float4*)(Er + (size_t)mg * HSIZE + f);
            erS[(f+0)*132 + mm] = ev.x;
            erS[(f+1)*132 + mm] = ev.y;
            erS[(f+2)*132 + mm] = ev.z;
            erS[(f+3)*132 + mm] = ev.w;
        }
        __syncthreads();

        float s[4][4];
        #pragma unroll
        for (int a = 0; a < 4; a++)
            #pragma unroll
            for (int b = 0; b < 4; b++) s[a][b] = 0.f;

        #pragma unroll 8
        for (int d = 0; d < 64; d++) {
            float4 qv = *(const float4*)&qT[d*68 + (ty << 2)];
            float4 kv = *(const float4*)&kT[d*68 + (tx << 2)];
            float4 e0 = *(const float4*)&erS[d*132 + erBase];
            float4 e1 = *(const float4*)&erS[d*132 + erBase + 4];
            float qa[4]  = {qv.x, qv.y, qv.z, qv.w};
            float ka[4]  = {kv.x, kv.y, kv.z, kv.w};
            float er8[8] = {e0.x, e0.y, e0.z, e0.w, e1.x, e1.y, e1.z, e1.w};
            #pragma unroll
            for (int a = 0; a < 4; a++)
                #pragma unroll
                for (int b = 0; b < 4; b++)
                    s[a][b] = fmaf(qa[a], ka[b] + er8[3 + b - a], s[a][b]);
        }

        const bool diag = (kt == qt);
        #pragma unroll
        for (int a = 0; a < 4; a++)
            #pragma unroll
            for (int b = 0; b < 4; b++) {
                float sv = s[a][b] * 0.125f;
                if (diag && ((tx << 2) + b) > ((ty << 2) + a)) sv = -INFINITY;
                s[a][b] = sv;
            }

        #pragma unroll
        for (int a = 0; a < 4; a++) {
            float mt = fmaxf(fmaxf(s[a][0], s[a][1]), fmaxf(s[a][2], s[a][3]));
            #pragma unroll
            for (int off = 8; off; off >>= 1)
                mt = fmaxf(mt, __shfl_xor_sync(0xffffffffu, mt, off));
            float mnew  = fmaxf(mrow[a], mt);
            float alpha = __expf(mrow[a] - mnew);
            mrow[a] = mnew;
            float ps = 0.f;
            #pragma unroll
            for (int b = 0; b < 4; b++) {
                float p = __expf(s[a][b] - mnew);
                s[a][b] = p;
                ps += p;
            }
            #pragma unroll
            for (int off = 8; off; off >>= 1)
                ps += __shfl_xor_sync(0xffffffffu, ps, off);
            lrow[a] = lrow[a] * alpha + ps;
            #pragma unroll
            for (int e = 0; e < 4; e++) o[a][e] *= alpha;
        }

        #pragma unroll
        for (int b = 0; b < 4; b++) {
            float4 pv = make_float4(s[0][b], s[1][b], s[2][b], s[3][b]);
            *(float4*)&pT[((tx << 2) + b)*68 + (ty << 2)] = pv;
        }
        __syncthreads();

        #pragma unroll 8
        for (int j = 0; j < 64; j++) {
            float4 pv = *(const float4*)&pT[j*68 + (ty << 2)];
            float4 vv = *(const float4*)&vS[j*68 + (tx << 2)];
            float pr[4] = {pv.x, pv.y, pv.z, pv.w};
            float vr[4] = {vv.x, vv.y, vv.z, vv.w};
            #pragma unroll
            for (int a = 0; a < 4; a++)
                #pragma unroll
                for (int e = 0; e < 4; e++)
                    o[a][e] = fmaf(pr[a], vr[e], o[a][e]);
        }
    }

    const int bb = bh >> 4;
    const int h  = bh & 15;
    #pragma unroll
    for (int a = 0; a < 4; a++) {
        float inv = 1.f / lrow[a];
        int row = i0 + (ty << 2) + a;
        float4 ov = make_float4(o[a][0]*inv, o[a][1]*inv, o[a][2]*inv, o[a][3]*inv);
        *(float4*)&g_Y[((size_t)bb*LSEQ + row)*DMODEL + (h << 6) + (tx << 2)] = ov;
    }
}

// ---------------------------------------------------------------------------
// Kernel 3: out = g_Y @ W_proj + b_proj (same quad layout, double-buffered)
// ---------------------------------------------------------------------------
__global__ __launch_bounds__(256, 2) void gemm_proj_kernel(
    const float* __restrict__ W, const float* __restrict__ bias,
    float* __restrict__ out)
{
    __shared__ float As[2][8][128];
    __shared__ float Bs[2][8][128];
    const int tid  = threadIdx.x;
    const int wid  = tid >> 5;
    const int lane = tid & 31;
    const int wm   = wid >> 2;
    const int wn   = wid & 3;
    const int lr   = lane >> 2;
    const int lc   = lane & 3;
    const int m0   = blockIdx.y * 128;
    const int n0   = blockIdx.x * 128;
    const int aBase = wm*64 + lr*4;
    const int bBase = wn*32 + lc*4;

    const int aRow = tid >> 1;
    const int aCol = (tid & 1) << 2;
    const int bRow = tid >> 5;
    const int bCol = (tid & 31) << 2;

    const float* Ap = g_Y + (size_t)(m0 + aRow) * DMODEL + aCol;
    const float* Bp = W + (size_t)bRow * DMODEL + n0 + bCol;

    float acc[8][8];
    #pragma unroll
    for (int i = 0; i < 8; i++)
        #pragma unroll
        for (int j = 0; j < 8; j++) acc[i][j] = 0.f;

    {
        float4 av = *(const float4*)(Ap);
        float4 bv = *(const float4*)(Bp);
        As[0][aCol+0][aRow] = av.x;
        As[0][aCol+1][aRow] = av.y;
        As[0][aCol+2][aRow] = av.z;
        As[0][aCol+3][aRow] = av.w;
        *(float4*)&Bs[0][bRow][bCol] = bv;
    }
    __syncthreads();

    const int NT = DMODEL / 8;   // 128
    for (int t = 0; t < NT; t++) {
        const int buf = t & 1;
        float4 anext, bnext;
        if (t + 1 < NT) {
            anext = *(const float4*)(Ap + (t+1)*8);
            bnext = *(const float4*)(Bp + (size_t)(t+1)*8*DMODEL);
        }
        #pragma unroll
        for (int kk = 0; kk < 8; kk++) {
            float a[8], b[8];
            *(float4*)&a[0] = *(const float4*)&As[buf][kk][aBase];
            *(float4*)&a[4] = *(const float4*)&As[buf][kk][aBase + 32];
            *(float4*)&b[0] = *(const float4*)&Bs[buf][kk][bBase];
            *(float4*)&b[4] = *(const float4*)&Bs[buf][kk][bBase + 16];
            #pragma unroll
            for (int i = 0; i < 8; i++)
                #pragma unroll
                for (int j = 0; j < 8; j++)
                    acc[i][j] = fmaf(a[i], b[j], acc[i][j]);
        }
        if (t + 1 < NT) {
            const int nb = buf ^ 1;
            As[nb][aCol+0][aRow] = anext.x;
            As[nb][aCol+1][aRow] = anext.y;
            As[nb][aCol+2][aRow] = anext.z;
            As[nb][aCol+3][aRow] = anext.w;
            *(float4*)&Bs[nb][bRow][bCol] = bnext;
        }
        __syncthreads();
    }

    #pragma unroll
    for (int i = 0; i < 8; i++) {
        const int m = m0 + aBase + ((i < 4) ? i : (28 + i));
        #pragma unroll
        for (int j4 = 0; j4 < 8; j4 += 4) {
            const int n = n0 + bBase + ((j4 == 0) ? 0 : 16);
            float4 ov;
            ov.x = acc[i][j4+0] + bias[n+0];
            ov.y = acc[i][j4+1] + bias[n+1];
            ov.z = acc[i][j4+2] + bias[n+2];
            ov.w = acc[i][j4+3] + bias[n+3];
            *(float4*)&out[(size_t)m * DMODEL + n] = ov;
        }
    }
}

// ---------------------------------------------------------------------------
extern "C" void kernel_launch(void* const* d_in, const int* in_sizes, int n_in,
                              void* d_out, int out_size)
{
    const float* x      = (const float*)d_in[0];
    const float* W_attn = (const float*)d_in[1];
    const float* b_attn = (const float*)d_in[2];
    const float* W_proj = (const float*)d_in[3];
    const float* b_proj = (const float*)d_in[4];
    const float* Er     = (const float*)d_in[5];
    float* out = (float*)d_out;

    (void)in_sizes; (void)n_in; (void)out_size;

    cudaFuncSetAttribute(attn_kernel,
                         cudaFuncAttributeMaxDynamicSharedMemorySize, 103424);

    gemm_qkv_kernel<<<dim3(24, 64), 256>>>(x, W_attn, b_attn);
    attn_kernel<<<dim3(32, 64), 256, 103424>>>(Er);
    gemm_proj_kernel<<<dim3(8, 64), 256>>>(W_proj, b_proj, out);
}

// round 9
// speedup vs baseline: 1.5367x; 1.5367x over previous
#include <cuda_runtime.h>
#include <math.h>
#include <cstdint>

#define LSEQ   2048
#define NB     4
#define DMODEL 1024
#define NH     16
#define HSIZE  64
#define MROWS  (NB*LSEQ)   // 8192

// Scratch (allocation-free rule: __device__ globals)
__device__ float g_Q[(size_t)NB*NH*LSEQ*HSIZE];
__device__ float g_K[(size_t)NB*NH*LSEQ*HSIZE];
__device__ float g_V[(size_t)NB*NH*LSEQ*HSIZE];
__device__ float g_Y[(size_t)MROWS*DMODEL];

// ---------------------------------------------------------------------------
// Packed fp32x2 helpers (Blackwell family-level PTX, compute_103-safe)
// ---------------------------------------------------------------------------
__device__ __forceinline__ uint64_t f2pk(float lo, float hi) {
    uint64_t r;
    asm("mov.b64 %0, {%1, %2};"
        : "=l"(r) : "r"(__float_as_uint(lo)), "r"(__float_as_uint(hi)));
    return r;
}
__device__ __forceinline__ void f2unpk(uint64_t v, float& lo, float& hi) {
    uint32_t a, b;
    asm("mov.b64 {%0, %1}, %2;" : "=r"(a), "=r"(b) : "l"(v));
    lo = __uint_as_float(a);
    hi = __uint_as_float(b);
}
__device__ __forceinline__ void ffma2(uint64_t& d, uint64_t a, uint64_t b) {
    asm("fma.rn.f32x2 %0, %1, %2, %0;" : "+l"(d) : "l"(a), "l"(b));
}
__device__ __forceinline__ uint64_t fadd2(uint64_t a, uint64_t b) {
    uint64_t r;
    asm("add.rn.f32x2 %0, %1, %2;" : "=l"(r) : "l"(a), "l"(b));
    return r;
}
__device__ __forceinline__ uint64_t fmul2(uint64_t a, uint64_t b) {
    uint64_t r;
    asm("mul.rn.f32x2 %0, %1, %2;" : "=l"(r) : "l"(a), "l"(b));
    return r;
}

// ---------------------------------------------------------------------------
// Kernel 1: qkv = x @ W_attn + b_attn, scattered into head-major Q/K/V.
// 128x128 tile, BK=8, 256 threads, 8x8 microtile (R2-measured-best layout),
// double-buffered smem, fp32x2 packed inner product.
// ---------------------------------------------------------------------------
__global__ __launch_bounds__(256, 2) void gemm_qkv_kernel(
    const float* __restrict__ X, const float* __restrict__ W,
    const float* __restrict__ bias)
{
    __shared__ float As[2][8][128];
    __shared__ float Bs[2][8][128];
    const int tid  = threadIdx.x;
    const int m0   = blockIdx.y * 128;
    const int n0   = blockIdx.x * 128;
    const int trow = tid >> 4;          // 0..15
    const int tcol = tid & 15;          // 0..15
    const int aRow = tid >> 1;          // 0..127
    const int aCol = (tid & 1) << 2;    // 0 or 4
    const int bRow = tid >> 5;          // 0..7
    const int bCol = (tid & 31) << 2;   // 0..124

    const float* Ap = X + (size_t)(m0 + aRow) * DMODEL + aCol;
    const float* Bp = W + (size_t)bRow * 3072 + n0 + bCol;

    uint64_t acc2[8][4];
    #pragma unroll
    for (int i = 0; i < 8; i++)
        #pragma unroll
        for (int jp = 0; jp < 4; jp++) acc2[i][jp] = 0ull;

    // prologue: tile 0 -> buffer 0
    {
        float4 av = *(const float4*)(Ap);
        float4 bv = *(const float4*)(Bp);
        As[0][aCol+0][aRow] = av.x;
        As[0][aCol+1][aRow] = av.y;
        As[0][aCol+2][aRow] = av.z;
        As[0][aCol+3][aRow] = av.w;
        *(float4*)&Bs[0][bRow][bCol] = bv;
    }
    __syncthreads();

    const int NT = DMODEL / 8;   // 128
    for (int t = 0; t < NT; t++) {
        const int buf = t & 1;
        float4 anext, bnext;
        if (t + 1 < NT) {
            anext = *(const float4*)(Ap + (t+1)*8);
            bnext = *(const float4*)(Bp + (size_t)(t+1)*8*3072);
        }
        #pragma unroll
        for (int kk = 0; kk < 8; kk++) {
            float a[8], b[8];
            *(float4*)&a[0] = *(const float4*)&As[buf][kk][trow*8];
            *(float4*)&a[4] = *(const float4*)&As[buf][kk][trow*8 + 4];
            *(float4*)&b[0] = *(const float4*)&Bs[buf][kk][tcol*8];
            *(float4*)&b[4] = *(const float4*)&Bs[buf][kk][tcol*8 + 4];
            uint64_t b2[4];
            #pragma unroll
            for (int jp = 0; jp < 4; jp++) b2[jp] = f2pk(b[2*jp], b[2*jp+1]);
            #pragma unroll
            for (int i = 0; i < 8; i++) {
                const uint64_t a2 = f2pk(a[i], a[i]);
                #pragma unroll
                for (int jp = 0; jp < 4; jp++)
                    ffma2(acc2[i][jp], a2, b2[jp]);
            }
        }
        if (t + 1 < NT) {
            const int nb = buf ^ 1;
            As[nb][aCol+0][aRow] = anext.x;
            As[nb][aCol+1][aRow] = anext.y;
            As[nb][aCol+2][aRow] = anext.z;
            As[nb][aCol+3][aRow] = anext.w;
            *(float4*)&Bs[nb][bRow][bCol] = bnext;
        }
        __syncthreads();
    }

    // Epilogue: scatter into head-major Q/K/V.
    const int chunk = n0 >> 10;
    float* dst = (chunk == 0) ? g_Q : (chunk == 1) ? g_K : g_V;
    #pragma unroll
    for (int i = 0; i < 8; i++) {
        float r8[8];
        #pragma unroll
        for (int jp = 0; jp < 4; jp++) f2unpk(acc2[i][jp], r8[2*jp], r8[2*jp+1]);
        const int m  = m0 + trow*8 + i;
        const int bb = m >> 11;
        const int l  = m & (LSEQ - 1);
        #pragma unroll
        for (int j4 = 0; j4 < 8; j4 += 4) {
            const int n = n0 + tcol*8 + j4;
            const int d = n - (chunk << 10);
            const int h = d >> 6;
            const int e = d & 63;
            float4 ov;
            ov.x = r8[j4+0] + bias[n+0];
            ov.y = r8[j4+1] + bias[n+1];
            ov.z = r8[j4+2] + bias[n+2];
            ov.w = r8[j4+3] + bias[n+3];
            *(float4*)&dst[((((size_t)bb*NH + h)*LSEQ + l) << 6) + e] = ov;
        }
    }
}

// ---------------------------------------------------------------------------
// Kernel 2: fused causal flash attention with relative-position band.
// Srel[i,j] = q_i . Er[L-1-i+j]  (j <= i), fused as  q . (k + er).
// Same structure as R2-passing version; S and PV loops use fp32x2.
// ---------------------------------------------------------------------------
__global__ __launch_bounds__(256) void attn_kernel(const float* __restrict__ Er)
{
    extern __shared__ float sm[];
    float* qT  = sm;            // [64][68]  qT[d][i]
    float* kT  = sm + 4352;     // [64][68]  kT[d][j]
    float* vS  = sm + 8704;     // [64][68]  vS[j][e]
    float* pT  = sm + 13056;    // [64][68]  pT[j][i]
    float* erS = sm + 17408;    // [64][132] erS[d][m], m in [0,127]

    const int tid = threadIdx.x;
    const int tx  = tid & 15;
    const int ty  = tid >> 4;
    const int qt  = blockIdx.x;
    const int bh  = blockIdx.y;
    const int i0  = qt << 6;

    const float* Qb = g_Q + (size_t)bh * LSEQ * HSIZE;
    const float* Kb = g_K + (size_t)bh * LSEQ * HSIZE;
    const float* Vb = g_V + (size_t)bh * LSEQ * HSIZE;

    #pragma unroll
    for (int r = 0; r < 4; r++) {
        int idx = tid + (r << 8);
        int row = idx >> 4;
        int f   = (idx & 15) << 2;
        float4 v = *(const float4*)(Qb + (size_t)(i0 + row) * HSIZE + f);
        qT[(f+0)*68 + row] = v.x;
        qT[(f+1)*68 + row] = v.y;
        qT[(f+2)*68 + row] = v.z;
        qT[(f+3)*68 + row] = v.w;
    }

    float mrow[4], lrow[4];
    uint64_t o2[4][2];
    #pragma unroll
    for (int a = 0; a < 4; a++) {
        mrow[a] = -INFINITY;
        lrow[a] = 0.f;
        o2[a][0] = 0ull;
        o2[a][1] = 0ull;
    }
    const int erBase = 60 + ((tx - ty) << 2);

    for (int kt = 0; kt <= qt; kt++) {
        const int j0 = kt << 6;
        __syncthreads();
        #pragma unroll
        for (int r = 0; r < 4; r++) {
            int idx = tid + (r << 8);
            int row = idx >> 4;
            int f   = (idx & 15) << 2;
            float4 kv = *(const float4*)(Kb + (size_t)(j0 + row) * HSIZE + f);
            kT[(f+0)*68 + row] = kv.x;
            kT[(f+1)*68 + row] = kv.y;
            kT[(f+2)*68 + row] = kv.z;
            kT[(f+3)*68 + row] = kv.w;
            float4 vv = *(const float4*)(Vb + (size_t)(j0 + row) * HSIZE + f);
            *(float4*)&vS[row*68 + f] = vv;
        }
        const int m_lo = LSEQ - 64 - i0 + j0;
        #pragma unroll
        for (int r = 0; r < 8; r++) {
            int idx = tid + (r << 8);
            int mm  = idx >> 4;
            int f   = (idx & 15) << 2;
            int mg  = m_lo + mm;
            float4 ev = make_float4(0.f, 0.f, 0.f, 0.f);
            if (mg < LSEQ)
                ev = *(const float4*)(Er + (size_t)mg * HSIZE + f);
            erS[(f+0)*132 + mm] = ev.x;
            erS[(f+1)*132 + mm] = ev.y;
            erS[(f+2)*132 + mm] = ev.z;
            erS[(f+3)*132 + mm] = ev.w;
        }
        __syncthreads();

        // S = q.(k + er), packed fp32x2 over key pairs
        uint64_t s2[4][2];
        #pragma unroll
        for (int a = 0; a < 4; a++) { s2[a][0] = 0ull; s2[a][1] = 0ull; }

        #pragma unroll 8
        for (int d = 0; d < 64; d++) {
            float4 qv = *(const float4*)&qT[d*68 + (ty << 2)];
            float4 kv = *(const float4*)&kT[d*68 + (tx << 2)];
            float4 e0 = *(const float4*)&erS[d*132 + erBase];
            float4 e1 = *(const float4*)&erS[d*132 + erBase + 4];
            float qa[4]  = {qv.x, qv.y, qv.z, qv.w};
            float er8[8] = {e0.x, e0.y, e0.z, e0.w, e1.x, e1.y, e1.z, e1.w};
            const uint64_t k2a = f2pk(kv.x, kv.y);
            const uint64_t k2b = f2pk(kv.z, kv.w);
            #pragma unroll
            for (int a = 0; a < 4; a++) {
                const uint64_t q2 = f2pk(qa[a], qa[a]);
                ffma2(s2[a][0], q2, fadd2(k2a, f2pk(er8[3-a], er8[4-a])));
                ffma2(s2[a][1], q2, fadd2(k2b, f2pk(er8[5-a], er8[6-a])));
            }
        }

        float s[4][4];
        #pragma unroll
        for (int a = 0; a < 4; a++) {
            f2unpk(s2[a][0], s[a][0], s[a][1]);
            f2unpk(s2[a][1], s[a][2], s[a][3]);
        }

        const bool diag = (kt == qt);
        #pragma unroll
        for (int a = 0; a < 4; a++)
            #pragma unroll
            for (int b = 0; b < 4; b++) {
                float sv = s[a][b] * 0.125f;
                if (diag && ((tx << 2) + b) > ((ty << 2) + a)) sv = -INFINITY;
                s[a][b] = sv;
            }

        #pragma unroll
        for (int a = 0; a < 4; a++) {
            float mt = fmaxf(fmaxf(s[a][0], s[a][1]), fmaxf(s[a][2], s[a][3]));
            #pragma unroll
            for (int off = 8; off; off >>= 1)
                mt = fmaxf(mt, __shfl_xor_sync(0xffffffffu, mt, off));
            float mnew  = fmaxf(mrow[a], mt);
            float alpha = __expf(mrow[a] - mnew);
            mrow[a] = mnew;
            float ps = 0.f;
            #pragma unroll
            for (int b = 0; b < 4; b++) {
                float p = __expf(s[a][b] - mnew);
                s[a][b] = p;
                ps += p;
            }
            #pragma unroll
            for (int off = 8; off; off >>= 1)
                ps += __shfl_xor_sync(0xffffffffu, ps, off);
            lrow[a] = lrow[a] * alpha + ps;
            const uint64_t al2 = f2pk(alpha, alpha);
            o2[a][0] = fmul2(o2[a][0], al2);
            o2[a][1] = fmul2(o2[a][1], al2);
        }

        #pragma unroll
        for (int b = 0; b < 4; b++) {
            float4 pv = make_float4(s[0][b], s[1][b], s[2][b], s[3][b]);
            *(float4*)&pT[((tx << 2) + b)*68 + (ty << 2)] = pv;
        }
        __syncthreads();

        // O += P @ V, packed fp32x2 over e pairs
        #pragma unroll 8
        for (int j = 0; j < 64; j++) {
            float4 pv = *(const float4*)&pT[j*68 + (ty << 2)];
            float4 vv = *(const float4*)&vS[j*68 + (tx << 2)];
            const uint64_t v2a = f2pk(vv.x, vv.y);
            const uint64_t v2b = f2pk(vv.z, vv.w);
            float pr[4] = {pv.x, pv.y, pv.z, pv.w};
            #pragma unroll
            for (int a = 0; a < 4; a++) {
                const uint64_t p2 = f2pk(pr[a], pr[a]);
                ffma2(o2[a][0], p2, v2a);
                ffma2(o2[a][1], p2, v2b);
            }
        }
    }

    const int bb = bh >> 4;
    const int h  = bh & 15;
    #pragma unroll
    for (int a = 0; a < 4; a++) {
        float inv = 1.f / lrow[a];
        float o0, o1, o2v, o3;
        f2unpk(o2[a][0], o0, o1);
        f2unpk(o2[a][1], o2v, o3);
        int row = i0 + (ty << 2) + a;
        float4 ov = make_float4(o0*inv, o1*inv, o2v*inv, o3*inv);
        *(float4*)&g_Y[((size_t)bb*LSEQ + row)*DMODEL + (h << 6) + (tx << 2)] = ov;
    }
}

// ---------------------------------------------------------------------------
// Kernel 3: out = g_Y @ W_proj + b_proj (same layout, fp32x2, double-buffered)
// ---------------------------------------------------------------------------
__global__ __launch_bounds__(256, 2) void gemm_proj_kernel(
    const float* __restrict__ W, const float* __restrict__ bias,
    float* __restrict__ out)
{
    __shared__ float As[2][8][128];
    __shared__ float Bs[2][8][128];
    const int tid  = threadIdx.x;
    const int m0   = blockIdx.y * 128;
    const int n0   = blockIdx.x * 128;
    const int trow = tid >> 4;
    const int tcol = tid & 15;
    const int aRow = tid >> 1;
    const int aCol = (tid & 1) << 2;
    const int bRow = tid >> 5;
    const int bCol = (tid & 31) << 2;

    const float* Ap = g_Y + (size_t)(m0 + aRow) * DMODEL + aCol;
    const float* Bp = W + (size_t)bRow * DMODEL + n0 + bCol;

    uint64_t acc2[8][4];
    #pragma unroll
    for (int i = 0; i < 8; i++)
        #pragma unroll
        for (int jp = 0; jp < 4; jp++) acc2[i][jp] = 0ull;

    {
        float4 av = *(const float4*)(Ap);
        float4 bv = *(const float4*)(Bp);
        As[0][aCol+0][aRow] = av.x;
        As[0][aCol+1][aRow] = av.y;
        As[0][aCol+2][aRow] = av.z;
        As[0][aCol+3][aRow] = av.w;
        *(float4*)&Bs[0][bRow][bCol] = bv;
    }
    __syncthreads();

    const int NT = DMODEL / 8;   // 128
    for (int t = 0; t < NT; t++) {
        const int buf = t & 1;
        float4 anext, bnext;
        if (t + 1 < NT) {
            anext = *(const float4*)(Ap + (t+1)*8);
            bnext = *(const float4*)(Bp + (size_t)(t+1)*8*DMODEL);
        }
        #pragma unroll
        for (int kk = 0; kk < 8; kk++) {
            float a[8], b[8];
            *(float4*)&a[0] = *(const float4*)&As[buf][kk][trow*8];
            *(float4*)&a[4] = *(const float4*)&As[buf][kk][trow*8 + 4];
            *(float4*)&b[0] = *(const float4*)&Bs[buf][kk][tcol*8];
            *(float4*)&b[4] = *(const float4*)&Bs[buf][kk][tcol*8 + 4];
            uint64_t b2[4];
            #pragma unroll
            for (int jp = 0; jp < 4; jp++) b2[jp] = f2pk(b[2*jp], b[2*jp+1]);
            #pragma unroll
            for (int i = 0; i < 8; i++) {
                const uint64_t a2 = f2pk(a[i], a[i]);
                #pragma unroll
                for (int jp = 0; jp < 4; jp++)
                    ffma2(acc2[i][jp], a2, b2[jp]);
            }
        }
        if (t + 1 < NT) {
            const int nb = buf ^ 1;
            As[nb][aCol+0][aRow] = anext.x;
            As[nb][aCol+1][aRow] = anext.y;
            As[nb][aCol+2][aRow] = anext.z;
            As[nb][aCol+3][aRow] = anext.w;
            *(float4*)&Bs[nb][bRow][bCol] = bnext;
        }
        __syncthreads();
    }

    #pragma unroll
    for (int i = 0; i < 8; i++) {
        float r8[8];
        #pragma unroll
        for (int jp = 0; jp < 4; jp++) f2unpk(acc2[i][jp], r8[2*jp], r8[2*jp+1]);
        const int m = m0 + trow*8 + i;
        #pragma unroll
        for (int j4 = 0; j4 < 8; j4 += 4) {
            const int n = n0 + tcol*8 + j4;
            float4 ov;
            ov.x = r8[j4+0] + bias[n+0];
            ov.y = r8[j4+1] + bias[n+1];
            ov.z = r8[j4+2] + bias[n+2];
            ov.w = r8[j4+3] + bias[n+3];
            *(float4*)&out[(size_t)m * DMODEL + n] = ov;
        }
    }
}

// ---------------------------------------------------------------------------
extern "C" void kernel_launch(void* const* d_in, const int* in_sizes, int n_in,
                              void* d_out, int out_size)
{
    const float* x      = (const float*)d_in[0];
    const float* W_attn = (const float*)d_in[1];
    const float* b_attn = (const float*)d_in[2];
    const float* W_proj = (const float*)d_in[3];
    const float* b_proj = (const float*)d_in[4];
    const float* Er     = (const float*)d_in[5];
    float* out = (float*)d_out;

    (void)in_sizes; (void)n_in; (void)out_size;

    cudaFuncSetAttribute(attn_kernel,
                         cudaFuncAttributeMaxDynamicSharedMemorySize, 103424);

    gemm_qkv_kernel<<<dim3(24, 64), 256>>>(x, W_attn, b_attn);
    attn_kernel<<<dim3(32, 64), 256, 103424>>>(Er);
    gemm_proj_kernel<<<dim3(8, 64), 256>>>(W_proj, b_proj, out);
}

// round 11
// speedup vs baseline: 1.6905x; 1.1001x over previous
#include <cuda_runtime.h>
#include <math.h>
#include <cstdint>

#define LSEQ   2048
#define NB     4
#define DMODEL 1024
#define NH     16
#define HSIZE  64
#define MROWS  (NB*LSEQ)   // 8192

// Scratch (allocation-free rule: __device__ globals)
__device__ float g_Q[(size_t)NB*NH*LSEQ*HSIZE];
__device__ float g_K[(size_t)NB*NH*LSEQ*HSIZE];
__device__ float g_V[(size_t)NB*NH*LSEQ*HSIZE];
__device__ float g_Y[(size_t)MROWS*DMODEL];

// ---------------------------------------------------------------------------
// Packed fp32x2 helpers (Blackwell family-level PTX, compute_103-safe)
// ---------------------------------------------------------------------------
__device__ __forceinline__ uint64_t f2pk(float lo, float hi) {
    uint64_t r;
    asm("mov.b64 %0, {%1, %2};"
        : "=l"(r) : "r"(__float_as_uint(lo)), "r"(__float_as_uint(hi)));
    return r;
}
__device__ __forceinline__ void f2unpk(uint64_t v, float& lo, float& hi) {
    uint32_t a, b;
    asm("mov.b64 {%0, %1}, %2;" : "=r"(a), "=r"(b) : "l"(v));
    lo = __uint_as_float(a);
    hi = __uint_as_float(b);
}
__device__ __forceinline__ void ffma2(uint64_t& d, uint64_t a, uint64_t b) {
    asm("fma.rn.f32x2 %0, %1, %2, %0;" : "+l"(d) : "l"(a), "l"(b));
}
__device__ __forceinline__ uint64_t fadd2(uint64_t a, uint64_t b) {
    uint64_t r;
    asm("add.rn.f32x2 %0, %1, %2;" : "=l"(r) : "l"(a), "l"(b));
    return r;
}
__device__ __forceinline__ uint64_t fmul2(uint64_t a, uint64_t b) {
    uint64_t r;
    asm("mul.rn.f32x2 %0, %1, %2;" : "=l"(r) : "l"(a), "l"(b));
    return r;
}

// ---------------------------------------------------------------------------
// Kernel 1: qkv = x @ W_attn + b_attn  (identical to R9 passing version)
// ---------------------------------------------------------------------------
__global__ __launch_bounds__(256, 2) void gemm_qkv_kernel(
    const float* __restrict__ X, const float* __restrict__ W,
    const float* __restrict__ bias)
{
    __shared__ float As[2][8][128];
    __shared__ float Bs[2][8][128];
    const int tid  = threadIdx.x;
    const int m0   = blockIdx.y * 128;
    const int n0   = blockIdx.x * 128;
    const int trow = tid >> 4;
    const int tcol = tid & 15;
    const int aRow = tid >> 1;
    const int aCol = (tid & 1) << 2;
    const int bRow = tid >> 5;
    const int bCol = (tid & 31) << 2;

    const float* Ap = X + (size_t)(m0 + aRow) * DMODEL + aCol;
    const float* Bp = W + (size_t)bRow * 3072 + n0 + bCol;

    uint64_t acc2[8][4];
    #pragma unroll
    for (int i = 0; i < 8; i++)
        #pragma unroll
        for (int jp = 0; jp < 4; jp++) acc2[i][jp] = 0ull;

    {
        float4 av = *(const float4*)(Ap);
        float4 bv = *(const float4*)(Bp);
        As[0][aCol+0][aRow] = av.x;
        As[0][aCol+1][aRow] = av.y;
        As[0][aCol+2][aRow] = av.z;
        As[0][aCol+3][aRow] = av.w;
        *(float4*)&Bs[0][bRow][bCol] = bv;
    }
    __syncthreads();

    const int NT = DMODEL / 8;
    for (int t = 0; t < NT; t++) {
        const int buf = t & 1;
        float4 anext, bnext;
        if (t + 1 < NT) {
            anext = *(const float4*)(Ap + (t+1)*8);
            bnext = *(const float4*)(Bp + (size_t)(t+1)*8*3072);
        }
        #pragma unroll
        for (int kk = 0; kk < 8; kk++) {
            float a[8], b[8];
            *(float4*)&a[0] = *(const float4*)&As[buf][kk][trow*8];
            *(float4*)&a[4] = *(const float4*)&As[buf][kk][trow*8 + 4];
            *(float4*)&b[0] = *(const float4*)&Bs[buf][kk][tcol*8];
            *(float4*)&b[4] = *(const float4*)&Bs[buf][kk][tcol*8 + 4];
            uint64_t b2[4];
            #pragma unroll
            for (int jp = 0; jp < 4; jp++) b2[jp] = f2pk(b[2*jp], b[2*jp+1]);
            #pragma unroll
            for (int i = 0; i < 8; i++) {
                const uint64_t a2 = f2pk(a[i], a[i]);
                #pragma unroll
                for (int jp = 0; jp < 4; jp++)
                    ffma2(acc2[i][jp], a2, b2[jp]);
            }
        }
        if (t + 1 < NT) {
            const int nb = buf ^ 1;
            As[nb][aCol+0][aRow] = anext.x;
            As[nb][aCol+1][aRow] = anext.y;
            As[nb][aCol+2][aRow] = anext.z;
            As[nb][aCol+3][aRow] = anext.w;
            *(float4*)&Bs[nb][bRow][bCol] = bnext;
        }
        __syncthreads();
    }

    const int chunk = n0 >> 10;
    float* dst = (chunk == 0) ? g_Q : (chunk == 1) ? g_K : g_V;
    #pragma unroll
    for (int i = 0; i < 8; i++) {
        float r8[8];
        #pragma unroll
        for (int jp = 0; jp < 4; jp++) f2unpk(acc2[i][jp], r8[2*jp], r8[2*jp+1]);
        const int m  = m0 + trow*8 + i;
        const int bb = m >> 11;
        const int l  = m & (LSEQ - 1);
        #pragma unroll
        for (int j4 = 0; j4 < 8; j4 += 4) {
            const int n = n0 + tcol*8 + j4;
            const int d = n - (chunk << 10);
            const int h = d >> 6;
            const int e = d & 63;
            float4 ov;
            ov.x = r8[j4+0] + bias[n+0];
            ov.y = r8[j4+1] + bias[n+1];
            ov.z = r8[j4+2] + bias[n+2];
            ov.w = r8[j4+3] + bias[n+3];
            *(float4*)&dst[((((size_t)bb*NH + h)*LSEQ + l) << 6) + e] = ov;
        }
    }
}

// ---------------------------------------------------------------------------
// Kernel 2: fused causal flash attention, 128x128 CTA tile, 8x8 thread tile.
// Srel[i,j] = q_i . Er[L-1-i+j] (j<=i), fused as q.(k+er).
// erS/kT columns chunk-XOR swizzled (c ^= (c>>3)&1) for 2-way-min conflicts.
// pS (row-major P[i][j]) aliases the kT+erS region; barriers sequence it.
// ---------------------------------------------------------------------------
#define AT_SMEM 168960

__global__ __launch_bounds__(256) void attn_kernel(const float* __restrict__ Er)
{
    extern __shared__ float sm[];
    float* qT  = sm;               // [64][132]  qT[d][i]
    float* kT  = sm + 8448;        // [64][132]  kT[d][swz(j)]   (aliased by pS)
    float* erS = sm + 16896;       // [64][260]  erS[d][swz(mm)] (partly aliased)
    float* pS  = sm + 8448;        // [128][132] pS[i][j]  (row-major P)
    float* vS  = sm + 33536;       // [128][68]  vS[j][e]

    const int tid = threadIdx.x;
    const int tx  = tid & 15;      // key-col group (8 cols) / e group (4 cols)
    const int ty  = tid >> 4;      // query-row group (8 rows)
    const int qt  = 15 - blockIdx.x;   // heavy tiles first
    const int bh  = blockIdx.y;
    const int i0  = qt << 7;

    const float* Qb = g_Q + (size_t)bh * LSEQ * HSIZE;
    const float* Kb = g_K + (size_t)bh * LSEQ * HSIZE;
    const float* Vb = g_V + (size_t)bh * LSEQ * HSIZE;

    // load q tile: qT[d][i], i in 0..127
    #pragma unroll
    for (int r = 0; r < 8; r++) {
        int idx = tid + (r << 8);
        int row = idx >> 4;
        int f   = (idx & 15) << 2;
        float4 v = *(const float4*)(Qb + (size_t)(i0 + row) * HSIZE + f);
        qT[(f+0)*132 + row] = v.x;
        qT[(f+1)*132 + row] = v.y;
        qT[(f+2)*132 + row] = v.z;
        qT[(f+3)*132 + row] = v.w;
    }

    float mrow[8], lrow[8];
    uint64_t o2[8][2];
    #pragma unroll
    for (int a = 0; a < 8; a++) {
        mrow[a] = -INFINITY; lrow[a] = 0.f;
        o2[a][0] = 0ull; o2[a][1] = 0ull;
    }

    // er window: mm(a,b) = 127 + 8*(tx-ty) + b - a; window base w0 = 120+8(tx-ty)
    const int ec0 = 30 + ((tx - ty) << 1);   // base 16B-chunk of window (in [0,60])

    for (int kt = 0; kt <= qt; kt++) {
        const int j0 = kt << 7;
        __syncthreads();   // prev iter's pS/vS/erS reads complete

        // fill kT (swizzled cols) + vS
        #pragma unroll
        for (int r = 0; r < 8; r++) {
            int idx = tid + (r << 8);
            int row = idx >> 4;             // j 0..127
            int f   = (idx & 15) << 2;      // d base
            float4 kv = *(const float4*)(Kb + (size_t)(j0 + row) * HSIZE + f);
            int c  = row >> 2;
            int cs = c ^ ((c >> 3) & 1);
            int colk = (cs << 2) | (row & 3);
            kT[(f+0)*132 + colk] = kv.x;
            kT[(f+1)*132 + colk] = kv.y;
            kT[(f+2)*132 + colk] = kv.z;
            kT[(f+3)*132 + colk] = kv.w;
            float4 vv = *(const float4*)(Vb + (size_t)(j0 + row) * HSIZE + f);
            *(float4*)&vS[row*68 + f] = vv;
        }
        // fill erS (swizzled cols), mm 0..255, global row mg = m_lo + mm
        const int m_lo = LSEQ - 128 - i0 + j0;   // >= 0 always
        #pragma unroll
        for (int r = 0; r < 16; r++) {
            int idx = tid + (r << 8);
            int mm  = idx >> 4;
            int f   = (idx & 15) << 2;
            int mg  = m_lo + mm;
            float4 ev = make_float4(0.f, 0.f, 0.f, 0.f);
            if (mg < LSEQ)
                ev = *(const float4*)(Er + (size_t)mg * HSIZE + f);
            int c  = mm >> 2;
            int cs = c ^ ((c >> 3) & 1);
            int cole = (cs << 2) | (mm & 3);
            erS[(f+0)*260 + cole] = ev.x;
            erS[(f+1)*260 + cole] = ev.y;
            erS[(f+2)*260 + cole] = ev.z;
            erS[(f+3)*260 + cole] = ev.w;
        }
        __syncthreads();

        // ---- S = q.(k + er), 8x8 per thread, f32x2 over key pairs ----
        uint64_t s2[8][4];
        #pragma unroll
        for (int a = 0; a < 8; a++)
            #pragma unroll
            for (int bp = 0; bp < 4; bp++) s2[a][bp] = 0ull;

        #pragma unroll 4
        for (int d = 0; d < 64; d++) {
            float q8[8], k8[8], er16[16];
            *(float4*)&q8[0] = *(const float4*)&qT[d*132 + (ty << 3)];
            *(float4*)&q8[4] = *(const float4*)&qT[d*132 + (ty << 3) + 4];
            {
                int c0 = tx << 1;
                int cs0 = c0 ^ ((c0 >> 3) & 1);
                int c1 = c0 + 1;
                int cs1 = c1 ^ ((c1 >> 3) & 1);
                *(float4*)&k8[0] = *(const float4*)&kT[d*132 + (cs0 << 2)];
                *(float4*)&k8[4] = *(const float4*)&kT[d*132 + (cs1 << 2)];
            }
            #pragma unroll
            for (int m = 0; m < 4; m++) {
                int c  = ec0 + m;
                int cs = c ^ ((c >> 3) & 1);
                *(float4*)&er16[m*4] = *(const float4*)&erS[d*260 + (cs << 2)];
            }
            uint64_t k2[4];
            #pragma unroll
            for (int bp = 0; bp < 4; bp++) k2[bp] = f2pk(k8[2*bp], k8[2*bp+1]);
            uint64_t EO[7], EE[7];
            #pragma unroll
            for (int s = 0; s < 7; s++) {
                EO[s] = f2pk(er16[2*s+1], er16[2*s+2]);
                EE[s] = f2pk(er16[2*s],   er16[2*s+1]);
            }
            #pragma unroll
            for (int a = 0; a < 8; a++) {
                const uint64_t q2 = f2pk(q8[a], q8[a]);
                const int a2 = a >> 1;
                if ((a & 1) == 0) {
                    #pragma unroll
                    for (int bp = 0; bp < 4; bp++)
                        ffma2(s2[a][bp], q2, fadd2(k2[bp], EO[3 + bp - a2]));
                } else {
                    #pragma unroll
                    for (int bp = 0; bp < 4; bp++)
                        ffma2(s2[a][bp], q2, fadd2(k2[bp], EE[3 + bp - a2]));
                }
            }
        }

        float s[8][8];
        #pragma unroll
        for (int a = 0; a < 8; a++)
            #pragma unroll
            for (int bp = 0; bp < 4; bp++)
                f2unpk(s2[a][bp], s[a][2*bp], s[a][2*bp+1]);

        const bool diag = (kt == qt);
        #pragma unroll
        for (int a = 0; a < 8; a++)
            #pragma unroll
            for (int b = 0; b < 8; b++) {
                float sv = s[a][b] * 0.125f;
                if (diag && ((tx << 3) + b) > ((ty << 3) + a)) sv = -INFINITY;
                s[a][b] = sv;
            }

        // online softmax, rows reduced over the 16 tx lanes
        #pragma unroll
        for (int a = 0; a < 8; a++) {
            float mt = s[a][0];
            #pragma unroll
            for (int b = 1; b < 8; b++) mt = fmaxf(mt, s[a][b]);
            #pragma unroll
            for (int off = 8; off; off >>= 1)
                mt = fmaxf(mt, __shfl_xor_sync(0xffffffffu, mt, off));
            float mnew  = fmaxf(mrow[a], mt);
            float alpha = __expf(mrow[a] - mnew);
            mrow[a] = mnew;
            float ps = 0.f;
            #pragma unroll
            for (int b = 0; b < 8; b++) {
                float p = __expf(s[a][b] - mnew);
                s[a][b] = p;
                ps += p;
            }
            #pragma unroll
            for (int off = 8; off; off >>= 1)
                ps += __shfl_xor_sync(0xffffffffu, ps, off);
            lrow[a] = lrow[a] * alpha + ps;
            const uint64_t al2 = f2pk(alpha, alpha);
            o2[a][0] = fmul2(o2[a][0], al2);
            o2[a][1] = fmul2(o2[a][1], al2);
        }

        __syncthreads();   // all kT/erS reads done before pS overwrites region
        #pragma unroll
        for (int a = 0; a < 8; a++) {
            *(float4*)&pS[((ty << 3) + a)*132 + (tx << 3)]     =
                make_float4(s[a][0], s[a][1], s[a][2], s[a][3]);
            *(float4*)&pS[((ty << 3) + a)*132 + (tx << 3) + 4] =
                make_float4(s[a][4], s[a][5], s[a][6], s[a][7]);
        }
        __syncthreads();

        // ---- O += P @ V : 8 rows x 4 e-cols per thread ----
        #pragma unroll 2
        for (int jb = 0; jb < 128; jb += 4) {
            float4 pa[8];
            #pragma unroll
            for (int a = 0; a < 8; a++)
                pa[a] = *(const float4*)&pS[((ty << 3) + a)*132 + jb];
            float4 vv[4];
            #pragma unroll
            for (int jj = 0; jj < 4; jj++)
                vv[jj] = *(const float4*)&vS[(jb + jj)*68 + (tx << 2)];
            uint64_t v2[4][2];
            #pragma unroll
            for (int jj = 0; jj < 4; jj++) {
                v2[jj][0] = f2pk(vv[jj].x, vv[jj].y);
                v2[jj][1] = f2pk(vv[jj].z, vv[jj].w);
            }
            #pragma unroll
            for (int a = 0; a < 8; a++) {
                float pr[4] = {pa[a].x, pa[a].y, pa[a].z, pa[a].w};
                #pragma unroll
                for (int jj = 0; jj < 4; jj++) {
                    const uint64_t p2 = f2pk(pr[jj], pr[jj]);
                    ffma2(o2[a][0], p2, v2[jj][0]);
                    ffma2(o2[a][1], p2, v2[jj][1]);
                }
            }
        }
    }

    // epilogue
    const int bb = bh >> 4;
    const int h  = bh & 15;
    #pragma unroll
    for (int a = 0; a < 8; a++) {
        float inv = 1.f / lrow[a];
        float o0, o1, o2v, o3;
        f2unpk(o2[a][0], o0, o1);
        f2unpk(o2[a][1], o2v, o3);
        int row = i0 + (ty << 3) + a;
        float4 ov = make_float4(o0*inv, o1*inv, o2v*inv, o3*inv);
        *(float4*)&g_Y[((size_t)bb*LSEQ + row)*DMODEL + (h << 6) + (tx << 2)] = ov;
    }
}

// ---------------------------------------------------------------------------
// Kernel 3: out = g_Y @ W_proj + b_proj  (identical to R9 passing version)
// ---------------------------------------------------------------------------
__global__ __launch_bounds__(256, 2) void gemm_proj_kernel(
    const float* __restrict__ W, const float* __restrict__ bias,
    float* __restrict__ out)
{
    __shared__ float As[2][8][128];
    __shared__ float Bs[2][8][128];
    const int tid  = threadIdx.x;
    const int m0   = blockIdx.y * 128;
    const int n0   = blockIdx.x * 128;
    const int trow = tid >> 4;
    const int tcol = tid & 15;
    const int aRow = tid >> 1;
    const int aCol = (tid & 1) << 2;
    const int bRow = tid >> 5;
    const int bCol = (tid & 31) << 2;

    const float* Ap = g_Y + (size_t)(m0 + aRow) * DMODEL + aCol;
    const float* Bp = W + (size_t)bRow * DMODEL + n0 + bCol;

    uint64_t acc2[8][4];
    #pragma unroll
    for (int i = 0; i < 8; i++)
        #pragma unroll
        for (int jp = 0; jp < 4; jp++) acc2[i][jp] = 0ull;

    {
        float4 av = *(const float4*)(Ap);
        float4 bv = *(const float4*)(Bp);
        As[0][aCol+0][aRow] = av.x;
        As[0][aCol+1][aRow] = av.y;
        As[0][aCol+2][aRow] = av.z;
        As[0][aCol+3][aRow] = av.w;
        *(float4*)&Bs[0][bRow][bCol] = bv;
    }
    __syncthreads();

    const int NT = DMODEL / 8;
    for (int t = 0; t < NT; t++) {
        const int buf = t & 1;
        float4 anext, bnext;
        if (t + 1 < NT) {
            anext = *(const float4*)(Ap + (t+1)*8);
            bnext = *(const float4*)(Bp + (size_t)(t+1)*8*DMODEL);
        }
        #pragma unroll
        for (int kk = 0; kk < 8; kk++) {
            float a[8], b[8];
            *(float4*)&a[0] = *(const float4*)&As[buf][kk][trow*8];
            *(float4*)&a[4] = *(const float4*)&As[buf][kk][trow*8 + 4];
            *(float4*)&b[0] = *(const float4*)&Bs[buf][kk][tcol*8];
            *(float4*)&b[4] = *(const float4*)&Bs[buf][kk][tcol*8 + 4];
            uint64_t b2[4];
            #pragma unroll
            for (int jp = 0; jp < 4; jp++) b2[jp] = f2pk(b[2*jp], b[2*jp+1]);
            #pragma unroll
            for (int i = 0; i < 8; i++) {
                const uint64_t a2 = f2pk(a[i], a[i]);
                #pragma unroll
                for (int jp = 0; jp < 4; jp++)
                    ffma2(acc2[i][jp], a2, b2[jp]);
            }
        }
        if (t + 1 < NT) {
            const int nb = buf ^ 1;
            As[nb][aCol+0][aRow] = anext.x;
            As[nb][aCol+1][aRow] = anext.y;
            As[nb][aCol+2][aRow] = anext.z;
            As[nb][aCol+3][aRow] = anext.w;
            *(float4*)&Bs[nb][bRow][bCol] = bnext;
        }
        __syncthreads();
    }

    #pragma unroll
    for (int i = 0; i < 8; i++) {
        float r8[8];
        #pragma unroll
        for (int jp = 0; jp < 4; jp++) f2unpk(acc2[i][jp], r8[2*jp], r8[2*jp+1]);
        const int m = m0 + trow*8 + i;
        #pragma unroll
        for (int j4 = 0; j4 < 8; j4 += 4) {
            const int n = n0 + tcol*8 + j4;
            float4 ov;
            ov.x = r8[j4+0] + bias[n+0];
            ov.y = r8[j4+1] + bias[n+1];
            ov.z = r8[j4+2] + bias[n+2];
            ov.w = r8[j4+3] + bias[n+3];
            *(float4*)&out[(size_t)m * DMODEL + n] = ov;
        }
    }
}

// ---------------------------------------------------------------------------
extern "C" void kernel_launch(void* const* d_in, const int* in_sizes, int n_in,
                              void* d_out, int out_size)
{
    const float* x      = (const float*)d_in[0];
    const float* W_attn = (const float*)d_in[1];
    const float* b_attn = (const float*)d_in[2];
    const float* W_proj = (const float*)d_in[3];
    const float* b_proj = (const float*)d_in[4];
    const float* Er     = (const float*)d_in[5];
    float* out = (float*)d_out;

    (void)in_sizes; (void)n_in; (void)out_size;

    cudaFuncSetAttribute(attn_kernel,
                         cudaFuncAttributeMaxDynamicSharedMemorySize, AT_SMEM);

    gemm_qkv_kernel<<<dim3(24, 64), 256>>>(x, W_attn, b_attn);
    attn_kernel<<<dim3(16, 64), 256, AT_SMEM>>>(Er);
    gemm_proj_kernel<<<dim3(8, 64), 256>>>(W_proj, b_proj, out);
}

// round 12
// speedup vs baseline: 1.8536x; 1.0965x over previous
#include <cuda_runtime.h>
#include <math.h>
#include <cstdint>

#define LSEQ   2048
#define NB     4
#define DMODEL 1024
#define NH     16
#define HSIZE  64
#define MROWS  (NB*LSEQ)   // 8192

// Scratch (allocation-free rule: __device__ globals)
__device__ float g_Q[(size_t)NB*NH*LSEQ*HSIZE];
__device__ float g_K[(size_t)NB*NH*LSEQ*HSIZE];
__device__ float g_V[(size_t)NB*NH*LSEQ*HSIZE];
__device__ float g_Y[(size_t)MROWS*DMODEL];

// ---------------------------------------------------------------------------
// Packed fp32x2 helpers (Blackwell family-level PTX, compute_103-safe)
// ---------------------------------------------------------------------------
__device__ __forceinline__ uint64_t f2pk(float lo, float hi) {
    uint64_t r;
    asm("mov.b64 %0, {%1, %2};"
        : "=l"(r) : "r"(__float_as_uint(lo)), "r"(__float_as_uint(hi)));
    return r;
}
__device__ __forceinline__ void f2unpk(uint64_t v, float& lo, float& hi) {
    uint32_t a, b;
    asm("mov.b64 {%0, %1}, %2;" : "=r"(a), "=r"(b) : "l"(v));
    lo = __uint_as_float(a);
    hi = __uint_as_float(b);
}
__device__ __forceinline__ void ffma2(uint64_t& d, uint64_t a, uint64_t b) {
    asm("fma.rn.f32x2 %0, %1, %2, %0;" : "+l"(d) : "l"(a), "l"(b));
}
__device__ __forceinline__ uint64_t fadd2(uint64_t a, uint64_t b) {
    uint64_t r;
    asm("add.rn.f32x2 %0, %1, %2;" : "=l"(r) : "l"(a), "l"(b));
    return r;
}
__device__ __forceinline__ uint64_t fmul2(uint64_t a, uint64_t b) {
    uint64_t r;
    asm("mul.rn.f32x2 %0, %1, %2;" : "=l"(r) : "l"(a), "l"(b));
    return r;
}

// ---------------------------------------------------------------------------
// Kernel 1: qkv = x @ W_attn + b_attn, head-major scatter epilogue.
// 128x128 tile, BK=8, 256 threads, QUAD fragment layout (R8-measured
// conflict-free: L1 69%) + f32x2 packed math (R9-measured issue halving).
// Warp grid 2x4 (wm,wn); lane grid 8x4 (lr,lc).
//   rows: wm*64 + lr*4 (+32)      cols: wn*32 + lc*4 (+16)
// ---------------------------------------------------------------------------
__global__ __launch_bounds__(256, 2) void gemm_qkv_kernel(
    const float* __restrict__ X, const float* __restrict__ W,
    const float* __restrict__ bias)
{
    __shared__ float As[2][8][128];
    __shared__ float Bs[2][8][128];
    const int tid  = threadIdx.x;
    const int wid  = tid >> 5;
    const int lane = tid & 31;
    const int wm   = wid >> 2;          // 0..1
    const int wn   = wid & 3;           // 0..3
    const int lr   = lane >> 2;         // 0..7
    const int lc   = lane & 3;          // 0..3
    const int m0   = blockIdx.y * 128;
    const int n0   = blockIdx.x * 128;
    const int aBase = wm*64 + lr*4;     // + {0,32}
    const int bBase = wn*32 + lc*4;     // + {0,16}

    const int aRow = tid >> 1;          // 0..127
    const int aCol = (tid & 1) << 2;    // 0 or 4
    const int bRow = tid >> 5;          // 0..7
    const int bCol = (tid & 31) << 2;   // 0..124

    const float* Ap = X + (size_t)(m0 + aRow) * DMODEL + aCol;
    const float* Bp = W + (size_t)bRow * 3072 + n0 + bCol;

    uint64_t acc2[8][4];
    #pragma unroll
    for (int i = 0; i < 8; i++)
        #pragma unroll
        for (int jp = 0; jp < 4; jp++) acc2[i][jp] = 0ull;

    {
        float4 av = *(const float4*)(Ap);
        float4 bv = *(const float4*)(Bp);
        As[0][aCol+0][aRow] = av.x;
        As[0][aCol+1][aRow] = av.y;
        As[0][aCol+2][aRow] = av.z;
        As[0][aCol+3][aRow] = av.w;
        *(float4*)&Bs[0][bRow][bCol] = bv;
    }
    __syncthreads();

    const int NT = DMODEL / 8;   // 128
    for (int t = 0; t < NT; t++) {
        const int buf = t & 1;
        float4 anext, bnext;
        if (t + 1 < NT) {
            anext = *(const float4*)(Ap + (t+1)*8);
            bnext = *(const float4*)(Bp + (size_t)(t+1)*8*3072);
        }
        #pragma unroll
        for (int kk = 0; kk < 8; kk++) {
            float a[8], b[8];
            *(float4*)&a[0] = *(const float4*)&As[buf][kk][aBase];
            *(float4*)&a[4] = *(const float4*)&As[buf][kk][aBase + 32];
            *(float4*)&b[0] = *(const float4*)&Bs[buf][kk][bBase];
            *(float4*)&b[4] = *(const float4*)&Bs[buf][kk][bBase + 16];
            uint64_t b2[4];
            #pragma unroll
            for (int jp = 0; jp < 4; jp++) b2[jp] = f2pk(b[2*jp], b[2*jp+1]);
            #pragma unroll
            for (int i = 0; i < 8; i++) {
                const uint64_t a2 = f2pk(a[i], a[i]);
                #pragma unroll
                for (int jp = 0; jp < 4; jp++)
                    ffma2(acc2[i][jp], a2, b2[jp]);
            }
        }
        if (t + 1 < NT) {
            const int nb = buf ^ 1;
            As[nb][aCol+0][aRow] = anext.x;
            As[nb][aCol+1][aRow] = anext.y;
            As[nb][aCol+2][aRow] = anext.z;
            As[nb][aCol+3][aRow] = anext.w;
            *(float4*)&Bs[nb][bRow][bCol] = bnext;
        }
        __syncthreads();
    }

    // Epilogue: scatter into head-major Q/K/V.
    // rows: i<4 -> aBase+i ; i>=4 -> aBase+32+(i-4)
    // cols: r8[0..3] -> bBase ; r8[4..7] -> bBase+16
    const int chunk = n0 >> 10;
    float* dst = (chunk == 0) ? g_Q : (chunk == 1) ? g_K : g_V;
    #pragma unroll
    for (int i = 0; i < 8; i++) {
        float r8[8];
        #pragma unroll
        for (int jp = 0; jp < 4; jp++) f2unpk(acc2[i][jp], r8[2*jp], r8[2*jp+1]);
        const int m  = m0 + aBase + ((i < 4) ? i : (28 + i));
        const int bb = m >> 11;
        const int l  = m & (LSEQ - 1);
        #pragma unroll
        for (int j4 = 0; j4 < 8; j4 += 4) {
            const int n = n0 + bBase + ((j4 == 0) ? 0 : 16);
            const int d = n - (chunk << 10);
            const int h = d >> 6;
            const int e = d & 63;
            float4 ov;
            ov.x = r8[j4+0] + bias[n+0];
            ov.y = r8[j4+1] + bias[n+1];
            ov.z = r8[j4+2] + bias[n+2];
            ov.w = r8[j4+3] + bias[n+3];
            *(float4*)&dst[((((size_t)bb*NH + h)*LSEQ + l) << 6) + e] = ov;
        }
    }
}

// ---------------------------------------------------------------------------
// Kernel 2: fused causal flash attention, 128x128 CTA tile, 8x8 thread tile
// (byte-identical to R11 passing version).
// ---------------------------------------------------------------------------
#define AT_SMEM 168960

__global__ __launch_bounds__(256) void attn_kernel(const float* __restrict__ Er)
{
    extern __shared__ float sm[];
    float* qT  = sm;               // [64][132]  qT[d][i]
    float* kT  = sm + 8448;        // [64][132]  kT[d][swz(j)]   (aliased by pS)
    float* erS = sm + 16896;       // [64][260]  erS[d][swz(mm)] (partly aliased)
    float* pS  = sm + 8448;        // [128][132] pS[i][j]  (row-major P)
    float* vS  = sm + 33536;       // [128][68]  vS[j][e]

    const int tid = threadIdx.x;
    const int tx  = tid & 15;
    const int ty  = tid >> 4;
    const int qt  = 15 - blockIdx.x;   // heavy tiles first
    const int bh  = blockIdx.y;
    const int i0  = qt << 7;

    const float* Qb = g_Q + (size_t)bh * LSEQ * HSIZE;
    const float* Kb = g_K + (size_t)bh * LSEQ * HSIZE;
    const float* Vb = g_V + (size_t)bh * LSEQ * HSIZE;

    #pragma unroll
    for (int r = 0; r < 8; r++) {
        int idx = tid + (r << 8);
        int row = idx >> 4;
        int f   = (idx & 15) << 2;
        float4 v = *(const float4*)(Qb + (size_t)(i0 + row) * HSIZE + f);
        qT[(f+0)*132 + row] = v.x;
        qT[(f+1)*132 + row] = v.y;
        qT[(f+2)*132 + row] = v.z;
        qT[(f+3)*132 + row] = v.w;
    }

    float mrow[8], lrow[8];
    uint64_t o2[8][2];
    #pragma unroll
    for (int a = 0; a < 8; a++) {
        mrow[a] = -INFINITY; lrow[a] = 0.f;
        o2[a][0] = 0ull; o2[a][1] = 0ull;
    }

    const int ec0 = 30 + ((tx - ty) << 1);

    for (int kt = 0; kt <= qt; kt++) {
        const int j0 = kt << 7;
        __syncthreads();

        #pragma unroll
        for (int r = 0; r < 8; r++) {
            int idx = tid + (r << 8);
            int row = idx >> 4;
            int f   = (idx & 15) << 2;
            float4 kv = *(const float4*)(Kb + (size_t)(j0 + row) * HSIZE + f);
            int c  = row >> 2;
            int cs = c ^ ((c >> 3) & 1);
            int colk = (cs << 2) | (row & 3);
            kT[(f+0)*132 + colk] = kv.x;
            kT[(f+1)*132 + colk] = kv.y;
            kT[(f+2)*132 + colk] = kv.z;
            kT[(f+3)*132 + colk] = kv.w;
            float4 vv = *(const float4*)(Vb + (size_t)(j0 + row) * HSIZE + f);
            *(float4*)&vS[row*68 + f] = vv;
        }
        const int m_lo = LSEQ - 128 - i0 + j0;
        #pragma unroll
        for (int r = 0; r < 16; r++) {
            int idx = tid + (r << 8);
            int mm  = idx >> 4;
            int f   = (idx & 15) << 2;
            int mg  = m_lo + mm;
            float4 ev = make_float4(0.f, 0.f, 0.f, 0.f);
            if (mg < LSEQ)
                ev = *(const float4*)(Er + (size_t)mg * HSIZE + f);
            int c  = mm >> 2;
            int cs = c ^ ((c >> 3) & 1);
            int cole = (cs << 2) | (mm & 3);
            erS[(f+0)*260 + cole] = ev.x;
            erS[(f+1)*260 + cole] = ev.y;
            erS[(f+2)*260 + cole] = ev.z;
            erS[(f+3)*260 + cole] = ev.w;
        }
        __syncthreads();

        uint64_t s2[8][4];
        #pragma unroll
        for (int a = 0; a < 8; a++)
            #pragma unroll
            for (int bp = 0; bp < 4; bp++) s2[a][bp] = 0ull;

        #pragma unroll 4
        for (int d = 0; d < 64; d++) {
            float q8[8], k8[8], er16[16];
            *(float4*)&q8[0] = *(const float4*)&qT[d*132 + (ty << 3)];
            *(float4*)&q8[4] = *(const float4*)&qT[d*132 + (ty << 3) + 4];
            {
                int c0 = tx << 1;
                int cs0 = c0 ^ ((c0 >> 3) & 1);
                int c1 = c0 + 1;
                int cs1 = c1 ^ ((c1 >> 3) & 1);
                *(float4*)&k8[0] = *(const float4*)&kT[d*132 + (cs0 << 2)];
                *(float4*)&k8[4] = *(const float4*)&kT[d*132 + (cs1 << 2)];
            }
            #pragma unroll
            for (int m = 0; m < 4; m++) {
                int c  = ec0 + m;
                int cs = c ^ ((c >> 3) & 1);
                *(float4*)&er16[m*4] = *(const float4*)&erS[d*260 + (cs << 2)];
            }
            uint64_t k2[4];
            #pragma unroll
            for (int bp = 0; bp < 4; bp++) k2[bp] = f2pk(k8[2*bp], k8[2*bp+1]);
            uint64_t EO[7], EE[7];
            #pragma unroll
            for (int s = 0; s < 7; s++) {
                EO[s] = f2pk(er16[2*s+1], er16[2*s+2]);
                EE[s] = f2pk(er16[2*s],   er16[2*s+1]);
            }
            #pragma unroll
            for (int a = 0; a < 8; a++) {
                const uint64_t q2 = f2pk(q8[a], q8[a]);
                const int a2 = a >> 1;
                if ((a & 1) == 0) {
                    #pragma unroll
                    for (int bp = 0; bp < 4; bp++)
                        ffma2(s2[a][bp], q2, fadd2(k2[bp], EO[3 + bp - a2]));
                } else {
                    #pragma unroll
                    for (int bp = 0; bp < 4; bp++)
                        ffma2(s2[a][bp], q2, fadd2(k2[bp], EE[3 + bp - a2]));
                }
            }
        }

        float s[8][8];
        #pragma unroll
        for (int a = 0; a < 8; a++)
            #pragma unroll
            for (int bp = 0; bp < 4; bp++)
                f2unpk(s2[a][bp], s[a][2*bp], s[a][2*bp+1]);

        const bool diag = (kt == qt);
        #pragma unroll
        for (int a = 0; a < 8; a++)
            #pragma unroll
            for (int b = 0; b < 8; b++) {
                float sv = s[a][b] * 0.125f;
                if (diag && ((tx << 3) + b) > ((ty << 3) + a)) sv = -INFINITY;
                s[a][b] = sv;
            }

        #pragma unroll
        for (int a = 0; a < 8; a++) {
            float mt = s[a][0];
            #pragma unroll
            for (int b = 1; b < 8; b++) mt = fmaxf(mt, s[a][b]);
            #pragma unroll
            for (int off = 8; off; off >>= 1)
                mt = fmaxf(mt, __shfl_xor_sync(0xffffffffu, mt, off));
            float mnew  = fmaxf(mrow[a], mt);
            float alpha = __expf(mrow[a] - mnew);
            mrow[a] = mnew;
            float ps = 0.f;
            #pragma unroll
            for (int b = 0; b < 8; b++) {
                float p = __expf(s[a][b] - mnew);
                s[a][b] = p;
                ps += p;
            }
            #pragma unroll
            for (int off = 8; off; off >>= 1)
                ps += __shfl_xor_sync(0xffffffffu, ps, off);
            lrow[a] = lrow[a] * alpha + ps;
            const uint64_t al2 = f2pk(alpha, alpha);
            o2[a][0] = fmul2(o2[a][0], al2);
            o2[a][1] = fmul2(o2[a][1], al2);
        }

        __syncthreads();
        #pragma unroll
        for (int a = 0; a < 8; a++) {
            *(float4*)&pS[((ty << 3) + a)*132 + (tx << 3)]     =
                make_float4(s[a][0], s[a][1], s[a][2], s[a][3]);
            *(float4*)&pS[((ty << 3) + a)*132 + (tx << 3) + 4] =
                make_float4(s[a][4], s[a][5], s[a][6], s[a][7]);
        }
        __syncthreads();

        #pragma unroll 2
        for (int jb = 0; jb < 128; jb += 4) {
            float4 pa[8];
            #pragma unroll
            for (int a = 0; a < 8; a++)
                pa[a] = *(const float4*)&pS[((ty << 3) + a)*132 + jb];
            float4 vv[4];
            #pragma unroll
            for (int jj = 0; jj < 4; jj++)
                vv[jj] = *(const float4*)&vS[(jb + jj)*68 + (tx << 2)];
            uint64_t v2[4][2];
            #pragma unroll
            for (int jj = 0; jj < 4; jj++) {
                v2[jj][0] = f2pk(vv[jj].x, vv[jj].y);
                v2[jj][1] = f2pk(vv[jj].z, vv[jj].w);
            }
            #pragma unroll
            for (int a = 0; a < 8; a++) {
                float pr[4] = {pa[a].x, pa[a].y, pa[a].z, pa[a].w};
                #pragma unroll
                for (int jj = 0; jj < 4; jj++) {
                    const uint64_t p2 = f2pk(pr[jj], pr[jj]);
                    ffma2(o2[a][0], p2, v2[jj][0]);
                    ffma2(o2[a][1], p2, v2[jj][1]);
                }
            }
        }
    }

    const int bb = bh >> 4;
    const int h  = bh & 15;
    #pragma unroll
    for (int a = 0; a < 8; a++) {
        float inv = 1.f / lrow[a];
        float o0, o1, o2v, o3;
        f2unpk(o2[a][0], o0, o1);
        f2unpk(o2[a][1], o2v, o3);
        int row = i0 + (ty << 3) + a;
        float4 ov = make_float4(o0*inv, o1*inv, o2v*inv, o3*inv);
        *(float4*)&g_Y[((size_t)bb*LSEQ + row)*DMODEL + (h << 6) + (tx << 2)] = ov;
    }
}

// ---------------------------------------------------------------------------
// Kernel 3: out = g_Y @ W_proj + b_proj (quad layout + f32x2)
// ---------------------------------------------------------------------------
__global__ __launch_bounds__(256, 2) void gemm_proj_kernel(
    const float* __restrict__ W, const float* __restrict__ bias,
    float* __restrict__ out)
{
    __shared__ float As[2][8][128];
    __shared__ float Bs[2][8][128];
    const int tid  = threadIdx.x;
    const int wid  = tid >> 5;
    const int lane = tid & 31;
    const int wm   = wid >> 2;
    const int wn   = wid & 3;
    const int lr   = lane >> 2;
    const int lc   = lane & 3;
    const int m0   = blockIdx.y * 128;
    const int n0   = blockIdx.x * 128;
    const int aBase = wm*64 + lr*4;
    const int bBase = wn*32 + lc*4;

    const int aRow = tid >> 1;
    const int aCol = (tid & 1) << 2;
    const int bRow = tid >> 5;
    const int bCol = (tid & 31) << 2;

    const float* Ap = g_Y + (size_t)(m0 + aRow) * DMODEL + aCol;
    const float* Bp = W + (size_t)bRow * DMODEL + n0 + bCol;

    uint64_t acc2[8][4];
    #pragma unroll
    for (int i = 0; i < 8; i++)
        #pragma unroll
        for (int jp = 0; jp < 4; jp++) acc2[i][jp] = 0ull;

    {
        float4 av = *(const float4*)(Ap);
        float4 bv = *(const float4*)(Bp);
        As[0][aCol+0][aRow] = av.x;
        As[0][aCol+1][aRow] = av.y;
        As[0][aCol+2][aRow] = av.z;
        As[0][aCol+3][aRow] = av.w;
        *(float4*)&Bs[0][bRow][bCol] = bv;
    }
    __syncthreads();

    const int NT = DMODEL / 8;
    for (int t = 0; t < NT; t++) {
        const int buf = t & 1;
        float4 anext, bnext;
        if (t + 1 < NT) {
            anext = *(const float4*)(Ap + (t+1)*8);
            bnext = *(const float4*)(Bp + (size_t)(t+1)*8*DMODEL);
        }
        #pragma unroll
        for (int kk = 0; kk < 8; kk++) {
            float a[8], b[8];
            *(float4*)&a[0] = *(const float4*)&As[buf][kk][aBase];
            *(float4*)&a[4] = *(const float4*)&As[buf][kk][aBase + 32];
            *(float4*)&b[0] = *(const float4*)&Bs[buf][kk][bBase];
            *(float4*)&b[4] = *(const float4*)&Bs[buf][kk][bBase + 16];
            uint64_t b2[4];
            #pragma unroll
            for (int jp = 0; jp < 4; jp++) b2[jp] = f2pk(b[2*jp], b[2*jp+1]);
            #pragma unroll
            for (int i = 0; i < 8; i++) {
                const uint64_t a2 = f2pk(a[i], a[i]);
                #pragma unroll
                for (int jp = 0; jp < 4; jp++)
                    ffma2(acc2[i][jp], a2, b2[jp]);
            }
        }
        if (t + 1 < NT) {
            const int nb = buf ^ 1;
            As[nb][aCol+0][aRow] = anext.x;
            As[nb][aCol+1][aRow] = anext.y;
            As[nb][aCol+2][aRow] = anext.z;
            As[nb][aCol+3][aRow] = anext.w;
            *(float4*)&Bs[nb][bRow][bCol] = bnext;
        }
        __syncthreads();
    }

    #pragma unroll
    for (int i = 0; i < 8; i++) {
        float r8[8];
        #pragma unroll
        for (int jp = 0; jp < 4; jp++) f2unpk(acc2[i][jp], r8[2*jp], r8[2*jp+1]);
        const int m = m0 + aBase + ((i < 4) ? i : (28 + i));
        #pragma unroll
        for (int j4 = 0; j4 < 8; j4 += 4) {
            const int n = n0 + bBase + ((j4 == 0) ? 0 : 16);
            float4 ov;
            ov.x = r8[j4+0] + bias[n+0];
            ov.y = r8[j4+1] + bias[n+1];
            ov.z = r8[j4+2] + bias[n+2];
            ov.w = r8[j4+3] + bias[n+3];
            *(float4*)&out[(size_t)m * DMODEL + n] = ov;
        }
    }
}

// ---------------------------------------------------------------------------
extern "C" void kernel_launch(void* const* d_in, const int* in_sizes, int n_in,
                              void* d_out, int out_size)
{
    const float* x      = (const float*)d_in[0];
    const float* W_attn = (const float*)d_in[1];
    const float* b_attn = (const float*)d_in[2];
    const float* W_proj = (const float*)d_in[3];
    const float* b_proj = (const float*)d_in[4];
    const float* Er     = (const float*)d_in[5];
    float* out = (float*)d_out;

    (void)in_sizes; (void)n_in; (void)out_size;

    cudaFuncSetAttribute(attn_kernel,
                         cudaFuncAttributeMaxDynamicSharedMemorySize, AT_SMEM);

    gemm_qkv_kernel<<<dim3(24, 64), 256>>>(x, W_attn, b_attn);
    attn_kernel<<<dim3(16, 64), 256, AT_SMEM>>>(Er);
    gemm_proj_kernel<<<dim3(8, 64), 256>>>(W_proj, b_proj, out);
}